// round 1
// baseline (speedup 1.0000x reference)
#include <cuda_runtime.h>
#include <math.h>

#define NTOK  8192
#define DDIM  512
#define HDIM  2048
#define NEXP  8
#define NPAIR 16384   // NTOK * top_k(2)

// ---------------- scratch (static device globals; no allocation) ----------------
__device__ int   g_counts[NEXP];
__device__ int   g_offsets[NEXP + 1];
__device__ int   g_cursor[NEXP];
__device__ int   g_sel[NPAIR];          // (token,k) -> expert
__device__ int   g_pair_token[NPAIR];   // pair row -> token
__device__ int   g_pair_expert[NPAIR];  // pair row -> expert
__device__ int   g_tok_pair[NPAIR];     // (token,k) -> pair row
__device__ float g_gate[NPAIR];         // (token,k) -> gate weight
__device__ float g_ss1[NPAIR];
__device__ float g_ss2[NPAIR];
__device__ float g_h1[(size_t)NPAIR * HDIM];  // 128 MB
__device__ float g_h2[(size_t)NPAIR * HDIM];  // 128 MB
__device__ float g_y [(size_t)NPAIR * DDIM];  // 32 MB

__device__ __forceinline__ float gelu_exact(float v) {
    return 0.5f * v * (1.0f + erff(v * 0.70710678118654752f));
}

// ---------------- setup kernels ----------------
__global__ void zero_kernel() {
    int idx = blockIdx.x * blockDim.x + threadIdx.x;
    if (idx < NPAIR) { g_ss1[idx] = 0.0f; g_ss2[idx] = 0.0f; }
    if (idx < NEXP)  { g_counts[idx] = 0; g_cursor[idx] = 0; }
}

// one warp per token: logits = x[t] @ gate_w, top-2, softmax
__global__ void gate_kernel(const float* __restrict__ x, const float* __restrict__ gw) {
    int t = blockIdx.x * 8 + (threadIdx.x >> 5);
    int lane = threadIdx.x & 31;
    if (t >= NTOK) return;
    float acc[NEXP];
#pragma unroll
    for (int e = 0; e < NEXP; ++e) acc[e] = 0.0f;
    const float* xr = x + (size_t)t * DDIM;
    for (int k = lane; k < DDIM; k += 32) {
        float xv = xr[k];
        const float* g = gw + k * NEXP;
#pragma unroll
        for (int e = 0; e < NEXP; ++e) acc[e] += xv * g[e];
    }
#pragma unroll
    for (int off = 16; off > 0; off >>= 1)
#pragma unroll
        for (int e = 0; e < NEXP; ++e)
            acc[e] += __shfl_xor_sync(0xFFFFFFFFu, acc[e], off);
    if (lane == 0) {
        int e0 = 0; float l0 = acc[0];
#pragma unroll
        for (int e = 1; e < NEXP; ++e) if (acc[e] > l0) { l0 = acc[e]; e0 = e; }
        int e1 = -1; float l1 = -1e30f;
#pragma unroll
        for (int e = 0; e < NEXP; ++e) if (e != e0 && acc[e] > l1) { l1 = acc[e]; e1 = e; }
        float p1 = __expf(l1 - l0);       // l0 >= l1
        float inv = 1.0f / (1.0f + p1);
        g_gate[t * 2 + 0] = inv;
        g_gate[t * 2 + 1] = p1 * inv;
        g_sel[t * 2 + 0] = e0;
        g_sel[t * 2 + 1] = e1;
        atomicAdd(&g_counts[e0], 1);
        atomicAdd(&g_counts[e1], 1);
    }
}

__global__ void offsets_kernel() {
    if (threadIdx.x == 0) {
        int s = 0;
        for (int e = 0; e < NEXP; ++e) { g_offsets[e] = s; s += g_counts[e]; }
        g_offsets[NEXP] = s;
    }
}

__global__ void scatter_kernel() {
    int idx = blockIdx.x * blockDim.x + threadIdx.x;
    if (idx >= NPAIR) return;
    int e = g_sel[idx];
    int pos = g_offsets[e] + atomicAdd(&g_cursor[e], 1);
    g_pair_token[pos] = idx >> 1;
    g_pair_expert[pos] = e;
    g_tok_pair[idx] = pos;
}

// ---------------- grouped GEMM ----------------
// MODE 1: C=g_h1 = x[gathered] @ w1[e]   (K=512,  N=2048) + gelu + sumsq
// MODE 2: C=g_h2 = g_h1 @ w2[e]          (K=2048, N=2048) + gelu + sumsq
// MODE 3: C=g_y  = g_h2 @ w3[e]          (K=2048, N=512)
template <int MODE>
__global__ __launch_bounds__(256, 2) void moe_gemm(
    const float* __restrict__ Xsrc, const float* __restrict__ Wsrc)
{
    constexpr int KD = (MODE == 1) ? DDIM : HDIM;
    constexpr int NC = (MODE == 3) ? DDIM : HDIM;
    constexpr bool GATHER = (MODE == 1);
    constexpr bool ACT = (MODE != 3);

    const int e = blockIdx.z;
    const int cnt = g_counts[e];
    const int row0 = blockIdx.y * 128;
    if (row0 >= cnt) return;
    const int off = g_offsets[e];
    const int n0 = blockIdx.x * 128;

    const float* Asrc = GATHER ? Xsrc : (MODE == 2 ? g_h1 : g_h2);
    float* C  = (MODE == 1) ? g_h1 : (MODE == 2 ? g_h2 : g_y);
    float* SS = (MODE == 1) ? g_ss1 : g_ss2;

    const float* B = Wsrc + (size_t)e * KD * NC;
    const int tid = threadIdx.x;

    // A tile load geometry (128 rows x 16 k)
    const int ar0 = tid >> 2;
    const int ar1 = ar0 + 64;
    const int ak  = (tid & 3) * 4;
    const int gr0 = row0 + ar0;
    const int gr1 = row0 + ar1;
    const bool v0 = gr0 < cnt;
    const bool v1 = gr1 < cnt;
    const float *arow0, *arow1;
    if (GATHER) {
        int t0 = v0 ? g_pair_token[off + gr0] : 0;
        int t1 = v1 ? g_pair_token[off + gr1] : 0;
        arow0 = Asrc + (size_t)t0 * KD;
        arow1 = Asrc + (size_t)t1 * KD;
    } else {
        arow0 = Asrc + (size_t)(off + (v0 ? gr0 : 0)) * KD;
        arow1 = Asrc + (size_t)(off + (v1 ? gr1 : 0)) * KD;
    }

    // B tile load geometry (16 k x 128 n)
    const int bkr = tid >> 5;
    const int bn  = (tid & 31) * 4;
    const float* bp = B + (size_t)bkr * NC + n0 + bn;

    __shared__ __align__(16) float As[2][16][132];
    __shared__ __align__(16) float Bs[2][16][132];
    __shared__ float rowss[128];

    float acc[8][8];
#pragma unroll
    for (int i = 0; i < 8; ++i)
#pragma unroll
        for (int j = 0; j < 8; ++j) acc[i][j] = 0.0f;

    // prologue
    {
        float4 a0 = *(const float4*)(arow0 + ak);
        float4 a1 = *(const float4*)(arow1 + ak);
        float4 b0 = *(const float4*)(bp);
        float4 b1 = *(const float4*)(bp + 8 * NC);
        As[0][ak + 0][ar0] = a0.x; As[0][ak + 1][ar0] = a0.y;
        As[0][ak + 2][ar0] = a0.z; As[0][ak + 3][ar0] = a0.w;
        As[0][ak + 0][ar1] = a1.x; As[0][ak + 1][ar1] = a1.y;
        As[0][ak + 2][ar1] = a1.z; As[0][ak + 3][ar1] = a1.w;
        *(float4*)&Bs[0][bkr][bn] = b0;
        *(float4*)&Bs[0][bkr + 8][bn] = b1;
    }
    __syncthreads();

    const int KT = KD / 16;
    int buf = 0;
    const int rb = (tid >> 4) * 8;
    const int cb = (tid & 15) * 8;

    for (int t = 0; t < KT; ++t) {
        float4 a0n, a1n, b0n, b1n;
        if (t + 1 < KT) {
            int k0 = (t + 1) * 16;
            a0n = *(const float4*)(arow0 + k0 + ak);
            a1n = *(const float4*)(arow1 + k0 + ak);
            b0n = *(const float4*)(bp + (size_t)k0 * NC);
            b1n = *(const float4*)(bp + (size_t)(k0 + 8) * NC);
        }
#pragma unroll
        for (int kk = 0; kk < 16; ++kk) {
            float4 a0 = *(const float4*)&As[buf][kk][rb];
            float4 a1 = *(const float4*)&As[buf][kk][rb + 4];
            float4 b0 = *(const float4*)&Bs[buf][kk][cb];
            float4 b1 = *(const float4*)&Bs[buf][kk][cb + 4];
            float av[8] = {a0.x, a0.y, a0.z, a0.w, a1.x, a1.y, a1.z, a1.w};
            float bv[8] = {b0.x, b0.y, b0.z, b0.w, b1.x, b1.y, b1.z, b1.w};
#pragma unroll
            for (int i = 0; i < 8; ++i)
#pragma unroll
                for (int j = 0; j < 8; ++j)
                    acc[i][j] = fmaf(av[i], bv[j], acc[i][j]);
        }
        if (t + 1 < KT) {
            int nb = buf ^ 1;
            As[nb][ak + 0][ar0] = a0n.x; As[nb][ak + 1][ar0] = a0n.y;
            As[nb][ak + 2][ar0] = a0n.z; As[nb][ak + 3][ar0] = a0n.w;
            As[nb][ak + 0][ar1] = a1n.x; As[nb][ak + 1][ar1] = a1n.y;
            As[nb][ak + 2][ar1] = a1n.z; As[nb][ak + 3][ar1] = a1n.w;
            *(float4*)&Bs[nb][bkr][bn] = b0n;
            *(float4*)&Bs[nb][bkr + 8][bn] = b1n;
            __syncthreads();
            buf = nb;
        }
    }

    // epilogue
    if (ACT) {
        if (tid < 128) rowss[tid] = 0.0f;
        __syncthreads();
    }
#pragma unroll
    for (int i = 0; i < 8; ++i) {
        int gr = row0 + rb + i;
        if (gr < cnt) {
            float v[8];
            float ssl = 0.0f;
#pragma unroll
            for (int j = 0; j < 8; ++j) {
                float w = acc[i][j];
                if (ACT) { w = gelu_exact(w); ssl += w * w; }
                v[j] = w;
            }
            float* crow = C + (size_t)(off + gr) * NC + n0 + cb;
            *(float4*)(crow)     = make_float4(v[0], v[1], v[2], v[3]);
            *(float4*)(crow + 4) = make_float4(v[4], v[5], v[6], v[7]);
            if (ACT) atomicAdd(&rowss[rb + i], ssl);
        }
    }
    if (ACT) {
        __syncthreads();
        if (tid < 128) {
            int gr = row0 + tid;
            if (gr < cnt) atomicAdd(&SS[off + gr], rowss[tid]);
        }
    }
}

// ---------------- rmsnorm scale kernels ----------------
__global__ void scale1_kernel(const float* __restrict__ n1) {
    int idx = blockIdx.x * blockDim.x + threadIdx.x;  // float4 index
    int p = idx / (HDIM / 4);
    int h = (idx % (HDIM / 4)) * 4;
    if (p >= NPAIR) return;
    int e = g_pair_expert[p];
    float rs = rsqrtf(g_ss1[p] * (1.0f / HDIM) + 1e-6f);
    size_t base = (size_t)p * HDIM + h;
    float4 v = *(float4*)&g_h1[base];
    const float* w = n1 + e * HDIM + h;
    v.x *= rs * w[0]; v.y *= rs * w[1]; v.z *= rs * w[2]; v.w *= rs * w[3];
    *(float4*)&g_h1[base] = v;
}

// h2 = rmsnorm(h2)*n2 + h1   (residual fused)
__global__ void scale2_kernel(const float* __restrict__ n2) {
    int idx = blockIdx.x * blockDim.x + threadIdx.x;
    int p = idx / (HDIM / 4);
    int h = (idx % (HDIM / 4)) * 4;
    if (p >= NPAIR) return;
    int e = g_pair_expert[p];
    float rs = rsqrtf(g_ss2[p] * (1.0f / HDIM) + 1e-6f);
    size_t base = (size_t)p * HDIM + h;
    float4 v = *(float4*)&g_h2[base];
    float4 r = *(const float4*)&g_h1[base];
    const float* w = n2 + e * HDIM + h;
    v.x = v.x * rs * w[0] + r.x;
    v.y = v.y * rs * w[1] + r.y;
    v.z = v.z * rs * w[2] + r.z;
    v.w = v.w * rs * w[3] + r.w;
    *(float4*)&g_h2[base] = v;
}

// ---------------- final gate-weighted combine ----------------
__global__ void combine_kernel(float* __restrict__ out) {
    int idx = blockIdx.x * blockDim.x + threadIdx.x;  // float4 index
    int t = idx / (DDIM / 4);
    int h = (idx % (DDIM / 4)) * 4;
    if (t >= NTOK) return;
    float go0 = g_gate[t * 2 + 0], go1 = g_gate[t * 2 + 1];
    int p0 = g_tok_pair[t * 2 + 0], p1 = g_tok_pair[t * 2 + 1];
    float4 y0 = *(const float4*)&g_y[(size_t)p0 * DDIM + h];
    float4 y1 = *(const float4*)&g_y[(size_t)p1 * DDIM + h];
    float4 r;
    r.x = go0 * y0.x + go1 * y1.x;
    r.y = go0 * y0.y + go1 * y1.y;
    r.z = go0 * y0.z + go1 * y1.z;
    r.w = go0 * y0.w + go1 * y1.w;
    *(float4*)&out[(size_t)t * DDIM + h] = r;
}

// ---------------- launcher ----------------
extern "C" void kernel_launch(void* const* d_in, const int* in_sizes, int n_in,
                              void* d_out, int out_size) {
    const float* x  = (const float*)d_in[0];
    const float* gw = (const float*)d_in[1];
    const float* w1 = (const float*)d_in[2];
    const float* w2 = (const float*)d_in[3];
    const float* w3 = (const float*)d_in[4];
    const float* n1 = (const float*)d_in[5];
    const float* n2 = (const float*)d_in[6];
    float* out = (float*)d_out;

    zero_kernel<<<(NPAIR + 255) / 256, 256>>>();
    gate_kernel<<<NTOK / 8, 256>>>(x, gw);
    offsets_kernel<<<1, 32>>>();
    scatter_kernel<<<NPAIR / 256, 256>>>();

    // worst case: one expert owns all NPAIR rows -> 128 row tiles
    moe_gemm<1><<<dim3(HDIM / 128, 128, NEXP), 256>>>(x, w1);
    scale1_kernel<<<NPAIR * (HDIM / 4) / 256, 256>>>(n1);
    moe_gemm<2><<<dim3(HDIM / 128, 128, NEXP), 256>>>(nullptr, w2);
    scale2_kernel<<<NPAIR * (HDIM / 4) / 256, 256>>>(n2);
    moe_gemm<3><<<dim3(DDIM / 128, 128, NEXP), 256>>>(nullptr, w3);

    combine_kernel<<<NTOK * (DDIM / 4) / 256, 256>>>(out);
}

// round 3
// speedup vs baseline: 2.3334x; 2.3334x over previous
#include <cuda_runtime.h>
#include <math.h>
#include <cstdint>

#define NTOK  8192
#define DDIM  512
#define HDIM  2048
#define NEXP  8
#define NPAIR 16384   // NTOK * top_k(2)

// GEMM tiles
#define BM 128
#define BN 128
#define BK 32
#define AROWF 36      // A SMEM row stride in floats (BK+4)
#define BROWF 136     // B SMEM row stride in floats (BN+8)
#define ABUF_BYTES (BM * AROWF * 4)          // 18432
#define BBUF_BYTES (BK * BROWF * 4)          // 17408
#define SMEM_DYN (2 * ABUF_BYTES + 2 * BBUF_BYTES)  // 71680

// ---------------- scratch (static device globals; no allocation) ----------------
__device__ int   g_counts[NEXP];
__device__ int   g_offsets[NEXP + 1];
__device__ int   g_cursor[NEXP];
__device__ int   g_sel[NPAIR];
__device__ int   g_pair_token[NPAIR];
__device__ int   g_pair_expert[NPAIR];
__device__ int   g_tok_pair[NPAIR];
__device__ float g_gate[NPAIR];
__device__ float g_ss1[NPAIR];
__device__ float g_ss2[NPAIR];
__device__ float g_h1[(size_t)NPAIR * HDIM];
__device__ float g_h2[(size_t)NPAIR * HDIM];
__device__ float g_y [(size_t)NPAIR * DDIM];

__device__ __forceinline__ float gelu_exact(float v) {
    return 0.5f * v * (1.0f + erff(v * 0.70710678118654752f));
}

__device__ __forceinline__ uint32_t smem_u32(const void* p) {
    uint32_t a;
    asm("{ .reg .u64 t; cvta.to.shared.u64 t, %1; cvt.u32.u64 %0, t; }" : "=r"(a) : "l"(p));
    return a;
}
__device__ __forceinline__ uint32_t f2tf(float f) {
    uint32_t r;
    asm("cvt.rna.tf32.f32 %0, %1;" : "=r"(r) : "f"(f));
    return r;
}
__device__ __forceinline__ void mma_tf32(float* c, uint32_t a0, uint32_t a1, uint32_t a2,
                                         uint32_t a3, uint32_t b0, uint32_t b1) {
    asm volatile(
        "mma.sync.aligned.m16n8k8.row.col.f32.tf32.tf32.f32 "
        "{%0,%1,%2,%3}, {%4,%5,%6,%7}, {%8,%9}, {%0,%1,%2,%3};"
        : "+f"(c[0]), "+f"(c[1]), "+f"(c[2]), "+f"(c[3])
        : "r"(a0), "r"(a1), "r"(a2), "r"(a3), "r"(b0), "r"(b1));
}

#define CP_ASYNC16(dst, src) \
    asm volatile("cp.async.cg.shared.global [%0], [%1], 16;" :: "r"(dst), "l"(src))
#define CP_COMMIT()  asm volatile("cp.async.commit_group;" ::: "memory")
#define CP_WAIT(n)   asm volatile("cp.async.wait_group %0;" :: "n"(n) : "memory")

// ---------------- setup kernels ----------------
__global__ void zero_kernel() {
    int idx = blockIdx.x * blockDim.x + threadIdx.x;
    if (idx < NPAIR) { g_ss1[idx] = 0.0f; g_ss2[idx] = 0.0f; }
    if (idx < NEXP)  { g_counts[idx] = 0; g_cursor[idx] = 0; }
}

__global__ void gate_kernel(const float* __restrict__ x, const float* __restrict__ gw) {
    int t = blockIdx.x * 8 + (threadIdx.x >> 5);
    int lane = threadIdx.x & 31;
    if (t >= NTOK) return;
    float acc[NEXP];
#pragma unroll
    for (int e = 0; e < NEXP; ++e) acc[e] = 0.0f;
    const float* xr = x + (size_t)t * DDIM;
    for (int k = lane; k < DDIM; k += 32) {
        float xv = xr[k];
        const float* g = gw + k * NEXP;
#pragma unroll
        for (int e = 0; e < NEXP; ++e) acc[e] += xv * g[e];
    }
#pragma unroll
    for (int off = 16; off > 0; off >>= 1)
#pragma unroll
        for (int e = 0; e < NEXP; ++e)
            acc[e] += __shfl_xor_sync(0xFFFFFFFFu, acc[e], off);
    if (lane == 0) {
        int e0 = 0; float l0 = acc[0];
#pragma unroll
        for (int e = 1; e < NEXP; ++e) if (acc[e] > l0) { l0 = acc[e]; e0 = e; }
        int e1 = -1; float l1 = -1e30f;
#pragma unroll
        for (int e = 0; e < NEXP; ++e) if (e != e0 && acc[e] > l1) { l1 = acc[e]; e1 = e; }
        float p1 = __expf(l1 - l0);
        float inv = 1.0f / (1.0f + p1);
        g_gate[t * 2 + 0] = inv;
        g_gate[t * 2 + 1] = p1 * inv;
        g_sel[t * 2 + 0] = e0;
        g_sel[t * 2 + 1] = e1;
        atomicAdd(&g_counts[e0], 1);
        atomicAdd(&g_counts[e1], 1);
    }
}

__global__ void offsets_kernel() {
    if (threadIdx.x == 0) {
        int s = 0;
        for (int e = 0; e < NEXP; ++e) { g_offsets[e] = s; s += g_counts[e]; }
        g_offsets[NEXP] = s;
    }
}

__global__ void scatter_kernel() {
    int idx = blockIdx.x * blockDim.x + threadIdx.x;
    if (idx >= NPAIR) return;
    int e = g_sel[idx];
    int pos = g_offsets[e] + atomicAdd(&g_cursor[e], 1);
    g_pair_token[pos] = idx >> 1;
    g_pair_expert[pos] = e;
    g_tok_pair[idx] = pos;
}

// ---------------- tf32 mma.sync grouped GEMM ----------------
// MODE 1: g_h1 = gelu(x[gathered] @ w1[e])   K=512,  N=2048  (+ sumsq)
// MODE 2: g_h2 = gelu(g_h1 @ w2[e])          K=2048, N=2048  (+ sumsq)
// MODE 3: g_y  = g_h2 @ w3[e]                K=2048, N=512
template <int MODE>
__global__ __launch_bounds__(256)
void moe_gemm_mma(const float* __restrict__ Xsrc, const float* __restrict__ Wsrc)
{
    constexpr int KD = (MODE == 1) ? DDIM : HDIM;
    constexpr int NC = (MODE == 3) ? DDIM : HDIM;
    constexpr bool GATHER = (MODE == 1);
    constexpr bool ACT = (MODE != 3);
    constexpr int KT = KD / BK;

    const int e = blockIdx.z;
    const int cnt = g_counts[e];
    const int row0 = blockIdx.y * BM;
    if (row0 >= cnt) return;
    const int off = g_offsets[e];
    const int n0 = blockIdx.x * BN;

    const float* Asrc = GATHER ? Xsrc : (MODE == 2 ? g_h1 : g_h2);
    float* C  = (MODE == 1) ? g_h1 : (MODE == 2 ? g_h2 : g_y);
    float* SS = (MODE == 1) ? g_ss1 : g_ss2;
    const float* B = Wsrc + (size_t)e * KD * NC;

    extern __shared__ char dynsmem[];
    float* As[2] = { (float*)dynsmem, (float*)(dynsmem + ABUF_BYTES) };
    float* Bs[2] = { (float*)(dynsmem + 2 * ABUF_BYTES),
                     (float*)(dynsmem + 2 * ABUF_BYTES + BBUF_BYTES) };
    const uint32_t sA[2] = { smem_u32(As[0]), smem_u32(As[1]) };
    const uint32_t sB[2] = { smem_u32(Bs[0]), smem_u32(Bs[1]) };

    const int tid = threadIdx.x;
    const int wid = tid >> 5;
    const int lane = tid & 31;
    const int qid = lane >> 2;        // 0..7
    const int tq  = lane & 3;         // 0..3
    const int warp_m = wid >> 2;      // 0..1 (64 rows each)
    const int warp_n = wid & 3;       // 0..3 (32 cols each)

    // --- A load geometry: 128 rows x 32 floats, 4x float4 per thread
    const float* aptr[4];
    uint32_t asw[4];
#pragma unroll
    for (int p = 0; p < 4; ++p) {
        int fidx = tid + p * 256;
        int row = fidx >> 3;          // 0..127
        int q   = fidx & 7;           // float4 within row
        int gr = row0 + row;
        int cr = (gr < cnt) ? gr : (cnt - 1);
        const float* base;
        if (GATHER) base = Xsrc + (size_t)g_pair_token[off + cr] * KD;
        else        base = Asrc + (size_t)(off + cr) * KD;
        aptr[p] = base + q * 4;
        asw[p] = (uint32_t)(row * AROWF + q * 4) * 4u;
    }
    // --- B load geometry: 32 k-rows x 128 cols, 4x float4 per thread
    const float* bptr[4];
    uint32_t bsw[4];
#pragma unroll
    for (int p = 0; p < 4; ++p) {
        int fidx = tid + p * 256;
        int krow = fidx >> 5;         // 0..31
        int n4   = fidx & 31;
        bptr[p] = B + (size_t)krow * NC + n0 + n4 * 4;
        bsw[p] = (uint32_t)(krow * BROWF + n4 * 4) * 4u;
    }

    float acc[4][4][4];
#pragma unroll
    for (int i = 0; i < 4; ++i)
#pragma unroll
        for (int j = 0; j < 4; ++j)
#pragma unroll
            for (int q = 0; q < 4; ++q) acc[i][j][q] = 0.0f;

    // prologue: chunk 0 -> buf 0
#pragma unroll
    for (int p = 0; p < 4; ++p) CP_ASYNC16(sA[0] + asw[p], aptr[p]);
#pragma unroll
    for (int p = 0; p < 4; ++p) CP_ASYNC16(sB[0] + bsw[p], bptr[p]);
    CP_COMMIT();

    const int m_base0 = warp_m * 64;
    const int n_base0 = warp_n * 32;

    for (int ch = 0; ch < KT; ++ch) {
        const int buf = ch & 1;
        if (ch + 1 < KT) {
            const int nb = (ch + 1) & 1;
            const int k0 = (ch + 1) * BK;
            const size_t bofs = (size_t)k0 * NC;
#pragma unroll
            for (int p = 0; p < 4; ++p) CP_ASYNC16(sA[nb] + asw[p], aptr[p] + k0);
#pragma unroll
            for (int p = 0; p < 4; ++p) CP_ASYNC16(sB[nb] + bsw[p], bptr[p] + bofs);
            CP_COMMIT();
            CP_WAIT(1);
        } else {
            CP_WAIT(0);
        }
        __syncthreads();

        const float* a = As[buf];
        const float* b = Bs[buf];
#pragma unroll
        for (int k8 = 0; k8 < 4; ++k8) {
            const int kb = k8 * 8;
            uint32_t ua[4][4], ub[4][2];
#pragma unroll
            for (int mt = 0; mt < 4; ++mt) {
                const int m = m_base0 + mt * 16 + qid;
                ua[mt][0] = f2tf(a[m * AROWF + kb + tq]);
                ua[mt][1] = f2tf(a[(m + 8) * AROWF + kb + tq]);
                ua[mt][2] = f2tf(a[m * AROWF + kb + tq + 4]);
                ua[mt][3] = f2tf(a[(m + 8) * AROWF + kb + tq + 4]);
            }
#pragma unroll
            for (int nt = 0; nt < 4; ++nt) {
                const int n = n_base0 + nt * 8 + qid;
                ub[nt][0] = f2tf(b[(kb + tq) * BROWF + n]);
                ub[nt][1] = f2tf(b[(kb + tq + 4) * BROWF + n]);
            }
#pragma unroll
            for (int mt = 0; mt < 4; ++mt)
#pragma unroll
                for (int nt = 0; nt < 4; ++nt)
                    mma_tf32(acc[mt][nt], ua[mt][0], ua[mt][1], ua[mt][2], ua[mt][3],
                             ub[nt][0], ub[nt][1]);
        }
        __syncthreads();
    }

    // --- epilogue ---
#pragma unroll
    for (int mt = 0; mt < 4; ++mt) {
        const int r0 = row0 + m_base0 + mt * 16 + qid;
        const int r1 = r0 + 8;
        float ss0 = 0.0f, ss1 = 0.0f;
#pragma unroll
        for (int nt = 0; nt < 4; ++nt) {
            const int col = n0 + n_base0 + nt * 8 + tq * 2;
            float v0 = acc[mt][nt][0], v1 = acc[mt][nt][1];
            float v2 = acc[mt][nt][2], v3 = acc[mt][nt][3];
            if (ACT) {
                v0 = gelu_exact(v0); v1 = gelu_exact(v1);
                v2 = gelu_exact(v2); v3 = gelu_exact(v3);
                ss0 += v0 * v0 + v1 * v1;
                ss1 += v2 * v2 + v3 * v3;
            }
            if (r0 < cnt) *(float2*)(C + (size_t)(off + r0) * NC + col) = make_float2(v0, v1);
            if (r1 < cnt) *(float2*)(C + (size_t)(off + r1) * NC + col) = make_float2(v2, v3);
        }
        if (ACT) {
#pragma unroll
            for (int o = 1; o < 4; o <<= 1) {
                ss0 += __shfl_xor_sync(0xFFFFFFFFu, ss0, o);
                ss1 += __shfl_xor_sync(0xFFFFFFFFu, ss1, o);
            }
            if (tq == 0) {
                if (r0 < cnt) atomicAdd(&SS[off + r0], ss0);
                if (r1 < cnt) atomicAdd(&SS[off + r1], ss1);
            }
        }
    }
}

// ---------------- rmsnorm scale kernels ----------------
__global__ void scale1_kernel(const float* __restrict__ n1) {
    int idx = blockIdx.x * blockDim.x + threadIdx.x;
    int p = idx / (HDIM / 4);
    int h = (idx % (HDIM / 4)) * 4;
    if (p >= NPAIR) return;
    int e = g_pair_expert[p];
    float rs = rsqrtf(g_ss1[p] * (1.0f / HDIM) + 1e-6f);
    size_t base = (size_t)p * HDIM + h;
    float4 v = *(float4*)&g_h1[base];
    const float* w = n1 + e * HDIM + h;
    v.x *= rs * w[0]; v.y *= rs * w[1]; v.z *= rs * w[2]; v.w *= rs * w[3];
    *(float4*)&g_h1[base] = v;
}

__global__ void scale2_kernel(const float* __restrict__ n2) {
    int idx = blockIdx.x * blockDim.x + threadIdx.x;
    int p = idx / (HDIM / 4);
    int h = (idx % (HDIM / 4)) * 4;
    if (p >= NPAIR) return;
    int e = g_pair_expert[p];
    float rs = rsqrtf(g_ss2[p] * (1.0f / HDIM) + 1e-6f);
    size_t base = (size_t)p * HDIM + h;
    float4 v = *(float4*)&g_h2[base];
    float4 r = *(const float4*)&g_h1[base];
    const float* w = n2 + e * HDIM + h;
    v.x = v.x * rs * w[0] + r.x;
    v.y = v.y * rs * w[1] + r.y;
    v.z = v.z * rs * w[2] + r.z;
    v.w = v.w * rs * w[3] + r.w;
    *(float4*)&g_h2[base] = v;
}

// ---------------- final gate-weighted combine ----------------
__global__ void combine_kernel(float* __restrict__ out) {
    int idx = blockIdx.x * blockDim.x + threadIdx.x;
    int t = idx / (DDIM / 4);
    int h = (idx % (DDIM / 4)) * 4;
    if (t >= NTOK) return;
    float go0 = g_gate[t * 2 + 0], go1 = g_gate[t * 2 + 1];
    int p0 = g_tok_pair[t * 2 + 0], p1 = g_tok_pair[t * 2 + 1];
    float4 y0 = *(const float4*)&g_y[(size_t)p0 * DDIM + h];
    float4 y1 = *(const float4*)&g_y[(size_t)p1 * DDIM + h];
    float4 r;
    r.x = go0 * y0.x + go1 * y1.x;
    r.y = go0 * y0.y + go1 * y1.y;
    r.z = go0 * y0.z + go1 * y1.z;
    r.w = go0 * y0.w + go1 * y1.w;
    *(float4*)&out[(size_t)t * DDIM + h] = r;
}

// ---------------- launcher ----------------
extern "C" void kernel_launch(void* const* d_in, const int* in_sizes, int n_in,
                              void* d_out, int out_size) {
    const float* x  = (const float*)d_in[0];
    const float* gw = (const float*)d_in[1];
    const float* w1 = (const float*)d_in[2];
    const float* w2 = (const float*)d_in[3];
    const float* w3 = (const float*)d_in[4];
    const float* n1 = (const float*)d_in[5];
    const float* n2 = (const float*)d_in[6];
    float* out = (float*)d_out;

    cudaFuncSetAttribute(moe_gemm_mma<1>, cudaFuncAttributeMaxDynamicSharedMemorySize, SMEM_DYN);
    cudaFuncSetAttribute(moe_gemm_mma<2>, cudaFuncAttributeMaxDynamicSharedMemorySize, SMEM_DYN);
    cudaFuncSetAttribute(moe_gemm_mma<3>, cudaFuncAttributeMaxDynamicSharedMemorySize, SMEM_DYN);

    zero_kernel<<<(NPAIR + 255) / 256, 256>>>();
    gate_kernel<<<NTOK / 8, 256>>>(x, gw);
    offsets_kernel<<<1, 32>>>();
    scatter_kernel<<<NPAIR / 256, 256>>>();

    moe_gemm_mma<1><<<dim3(HDIM / BN, NPAIR / BM, NEXP), 256, SMEM_DYN>>>(x, w1);
    scale1_kernel<<<NPAIR * (HDIM / 4) / 256, 256>>>(n1);
    moe_gemm_mma<2><<<dim3(HDIM / BN, NPAIR / BM, NEXP), 256, SMEM_DYN>>>(nullptr, w2);
    scale2_kernel<<<NPAIR * (HDIM / 4) / 256, 256>>>(n2);
    moe_gemm_mma<3><<<dim3(DDIM / BN, NPAIR / BM, NEXP), 256, SMEM_DYN>>>(nullptr, w3);

    combine_kernel<<<NTOK * (DDIM / 4) / 256, 256>>>(out);
}

// round 17
// speedup vs baseline: 3.9298x; 1.6842x over previous
#include <cuda_runtime.h>
#include <cuda_fp16.h>
#include <math.h>
#include <cstdint>

#define NTOK  8192
#define DDIM  512
#define HDIM  2048
#define NEXP  8
#define NPAIR 16384   // NTOK * top_k(2)

// GEMM tiles
#define BM 128
#define BN 128
#define BK 32
#define AROW 40       // SMEM row stride in halves (BK + 8) -> 80B rows, 16B aligned
#define TILE_BYTES (128 * AROW * 2)          // 10240
#define SMEM_DYN (4 * TILE_BYTES)            // 40960 < 48KB default limit

// ---------------- scratch (static device globals; no allocation) ----------------
// RULE: these symbols are referenced ONLY inside device code. Passing them as
// kernel arguments from host code silently binds the host-side shadow object
// (GB300 ATS makes that a valid-but-wrong host address) — root cause of all
// previous fp16 failures.
__device__ int    g_counts[NEXP];
__device__ int    g_offsets[NEXP + 1];
__device__ int    g_cursor[NEXP];
__device__ int    g_sel[NPAIR];
__device__ int    g_pair_token[NPAIR];
__device__ int    g_pair_expert[NPAIR];
__device__ int    g_tok_pair[NPAIR];
__device__ float  g_gate[NPAIR];
__device__ float  g_ss1[NPAIR];
__device__ float  g_ss2[NPAIR];
__device__ float  g_y [(size_t)NPAIR * DDIM];    // fp32 expert outputs
__device__ __half g_xh [(size_t)NTOK * DDIM];    // x fp16
__device__ __half g_h1r[(size_t)NPAIR * HDIM];   // gelu(x@w1) fp16
__device__ __half g_h1h[(size_t)NPAIR * HDIM];   // rmsnorm(h1)*n1 fp16 (GEMM2 A + residual)
__device__ __half g_h2r[(size_t)NPAIR * HDIM];   // gelu(h1h@w2) fp16
__device__ __half g_s2h[(size_t)NPAIR * HDIM];   // rmsnorm(h2)*n2+h1h fp16 (GEMM3 A)
__device__ __half g_w1t[(size_t)NEXP * HDIM * DDIM];  // [e][n=H][k=D]
__device__ __half g_w2t[(size_t)NEXP * HDIM * HDIM];  // [e][n=H][k=H]
__device__ __half g_w3t[(size_t)NEXP * DDIM * HDIM];  // [e][n=D][k=H]

__device__ __forceinline__ float gelu_exact(float v) {
    return 0.5f * v * (1.0f + erff(v * 0.70710678118654752f));
}
__device__ __forceinline__ uint32_t smem_u32(const void* p) {
    uint32_t a;
    asm("{ .reg .u64 t; cvta.to.shared.u64 t, %1; cvt.u32.u64 %0, t; }" : "=r"(a) : "l"(p));
    return a;
}
__device__ __forceinline__ void mma_f16(float* c, uint32_t a0, uint32_t a1, uint32_t a2,
                                        uint32_t a3, uint32_t b0, uint32_t b1) {
    asm volatile(
        "mma.sync.aligned.m16n8k16.row.col.f32.f16.f16.f32 "
        "{%0,%1,%2,%3}, {%4,%5,%6,%7}, {%8,%9}, {%0,%1,%2,%3};"
        : "+f"(c[0]), "+f"(c[1]), "+f"(c[2]), "+f"(c[3])
        : "r"(a0), "r"(a1), "r"(a2), "r"(a3), "r"(b0), "r"(b1));
}
#define CP_ASYNC16(dst, src) \
    asm volatile("cp.async.cg.shared.global [%0], [%1], 16;" :: "r"(dst), "l"(src))
#define CP_COMMIT()  asm volatile("cp.async.commit_group;" ::: "memory")
#define CP_WAIT(n)   asm volatile("cp.async.wait_group %0;" :: "n"(n) : "memory")

// ---------------- setup kernels ----------------
__global__ void zero_kernel() {
    int idx = blockIdx.x * blockDim.x + threadIdx.x;
    if (idx < NPAIR) { g_ss1[idx] = 0.0f; g_ss2[idx] = 0.0f; }
    if (idx < NEXP)  { g_counts[idx] = 0; g_cursor[idx] = 0; }
}

__global__ void gate_kernel(const float* __restrict__ x, const float* __restrict__ gw) {
    int t = blockIdx.x * 8 + (threadIdx.x >> 5);
    int lane = threadIdx.x & 31;
    if (t >= NTOK) return;
    float acc[NEXP];
#pragma unroll
    for (int e = 0; e < NEXP; ++e) acc[e] = 0.0f;
    const float* xr = x + (size_t)t * DDIM;
    for (int k = lane; k < DDIM; k += 32) {
        float xv = xr[k];
        const float* g = gw + k * NEXP;
#pragma unroll
        for (int e = 0; e < NEXP; ++e) acc[e] += xv * g[e];
    }
#pragma unroll
    for (int off = 16; off > 0; off >>= 1)
#pragma unroll
        for (int e = 0; e < NEXP; ++e)
            acc[e] += __shfl_xor_sync(0xFFFFFFFFu, acc[e], off);
    if (lane == 0) {
        int e0 = 0; float l0 = acc[0];
#pragma unroll
        for (int e = 1; e < NEXP; ++e) if (acc[e] > l0) { l0 = acc[e]; e0 = e; }
        int e1 = -1; float l1 = -1e30f;
#pragma unroll
        for (int e = 0; e < NEXP; ++e) if (e != e0 && acc[e] > l1) { l1 = acc[e]; e1 = e; }
        float p1 = __expf(l1 - l0);
        float inv = 1.0f / (1.0f + p1);
        g_gate[t * 2 + 0] = inv;
        g_gate[t * 2 + 1] = p1 * inv;
        g_sel[t * 2 + 0] = e0;
        g_sel[t * 2 + 1] = e1;
        atomicAdd(&g_counts[e0], 1);
        atomicAdd(&g_counts[e1], 1);
    }
}

__global__ void offsets_kernel() {
    if (threadIdx.x == 0) {
        int s = 0;
        for (int e = 0; e < NEXP; ++e) { g_offsets[e] = s; s += g_counts[e]; }
        g_offsets[NEXP] = s;
    }
}

__global__ void scatter_kernel() {
    int idx = blockIdx.x * blockDim.x + threadIdx.x;
    if (idx >= NPAIR) return;
    int e = g_sel[idx];
    int pos = g_offsets[e] + atomicAdd(&g_cursor[e], 1);
    g_pair_token[pos] = idx >> 1;
    g_pair_expert[pos] = e;
    g_tok_pair[idx] = pos;
}

// ---------------- conversion kernels ----------------
__global__ void convert_x_kernel(const float* __restrict__ x) {
    int idx = blockIdx.x * blockDim.x + threadIdx.x;   // 4 elems per thread
    size_t base = (size_t)idx * 4;
    if (base >= (size_t)NTOK * DDIM) return;
    float4 v = *(const float4*)(x + base);
    __half2 h0 = __floats2half2_rn(v.x, v.y);
    __half2 h1 = __floats2half2_rn(v.z, v.w);
    *(uint2*)&g_xh[base] = make_uint2(*(uint32_t*)&h0, *(uint32_t*)&h1);
}

// w[e][KD][NC] (fp32) -> g_wXt[e][NC][KD] (fp16); destination chosen in DEVICE code
template <int KD, int NC, int WHICH>
__global__ void transpose_w_kernel(const float* __restrict__ w) {
    __half* wt = (WHICH == 1) ? g_w1t : (WHICH == 2) ? g_w2t : g_w3t;
    __shared__ float t[32][33];
    const int e = blockIdx.z;
    const int n0 = blockIdx.x * 32;
    const int k0 = blockIdx.y * 32;
    const int tx = threadIdx.x, ty = threadIdx.y;
    const float* src = w + (size_t)e * KD * NC;
    __half* dst = wt + (size_t)e * NC * KD;
#pragma unroll
    for (int j = 0; j < 4; ++j)
        t[ty + j * 8][tx] = src[(size_t)(k0 + ty + j * 8) * NC + n0 + tx];
    __syncthreads();
#pragma unroll
    for (int j = 0; j < 4; ++j)
        dst[(size_t)(n0 + ty + j * 8) * KD + k0 + tx] = __float2half_rn(t[tx][ty + j * 8]);
}

// ---------------- fp16 mma.sync grouped GEMM ----------------
// MODE 1: g_h1r = fp16(gelu(xh[gathered] @ w1t[e]^T))  K=512,  N=2048  (+ sumsq)
// MODE 2: g_h2r = fp16(gelu(h1h @ w2t[e]^T))           K=2048, N=2048  (+ sumsq)
// MODE 3: g_y   = s2h @ w3t[e]^T  (fp32 out)           K=2048, N=512
template <int MODE>
__global__ __launch_bounds__(256)
void moe_gemm_h(void)
{
    constexpr int KD = (MODE == 1) ? DDIM : HDIM;
    constexpr int NC = (MODE == 3) ? DDIM : HDIM;
    constexpr bool GATHER = (MODE == 1);
    constexpr bool ACT = (MODE != 3);
    constexpr int KT = KD / BK;

    const int e = blockIdx.z;
    const int cnt = g_counts[e];
    const int row0 = blockIdx.y * BM;
    if (row0 >= cnt) return;
    const int off = g_offsets[e];
    const int n0 = blockIdx.x * BN;

    const __half* Asrc = GATHER ? g_xh : (MODE == 2 ? g_h1h : g_s2h);
    const __half* Wt   = (MODE == 1) ? g_w1t : (MODE == 2 ? g_w2t : g_w3t);
    __half* Ch = (MODE == 1) ? g_h1r : g_h2r;   // fp16 out (ACT modes)
    float*  Cf = g_y;                            // fp32 out (MODE 3)
    float* SS = (MODE == 1) ? g_ss1 : g_ss2;
    const __half* B = Wt + (size_t)e * NC * KD;  // [NC][KD]

    extern __shared__ char dynsmem[];
    __half* As[2] = { (__half*)dynsmem, (__half*)(dynsmem + TILE_BYTES) };
    __half* Bs[2] = { (__half*)(dynsmem + 2 * TILE_BYTES),
                      (__half*)(dynsmem + 3 * TILE_BYTES) };
    const uint32_t sA[2] = { smem_u32(As[0]), smem_u32(As[1]) };
    const uint32_t sB[2] = { smem_u32(Bs[0]), smem_u32(Bs[1]) };

    const int tid = threadIdx.x;
    const int wid = tid >> 5;
    const int lane = tid & 31;
    const int qid = lane >> 2;
    const int tq  = lane & 3;
    const int warp_m = wid >> 2;     // 0..1: 64 rows
    const int warp_n = wid & 3;      // 0..3: 32 cols

    // --- load geometry: tile = 128 rows x 32 halves (64B/row), 4x16B chunks/row
    const __half* aptr[2];
    const __half* bptr[2];
    uint32_t asw[2];
#pragma unroll
    for (int p = 0; p < 2; ++p) {
        int fidx = tid + p * 256;
        int row = fidx >> 2;          // 0..127
        int c   = fidx & 3;
        int gr = row0 + row;
        int cr = (gr < cnt) ? gr : (cnt - 1);
        const __half* base;
        if (GATHER) base = Asrc + (size_t)g_pair_token[off + cr] * KD;
        else        base = Asrc + (size_t)(off + cr) * KD;
        aptr[p] = base + c * 8;
        bptr[p] = B + (size_t)(n0 + row) * KD + c * 8;
        asw[p] = (uint32_t)(row * AROW + c * 8) * 2u;
    }

    float acc[4][4][4];
#pragma unroll
    for (int i = 0; i < 4; ++i)
#pragma unroll
        for (int j = 0; j < 4; ++j)
#pragma unroll
            for (int q = 0; q < 4; ++q) acc[i][j][q] = 0.0f;

    // prologue
#pragma unroll
    for (int p = 0; p < 2; ++p) CP_ASYNC16(sA[0] + asw[p], aptr[p]);
#pragma unroll
    for (int p = 0; p < 2; ++p) CP_ASYNC16(sB[0] + asw[p], bptr[p]);
    CP_COMMIT();

    const int m_base = warp_m * 64;
    const int n_base = warp_n * 32;

    for (int ch = 0; ch < KT; ++ch) {
        const int buf = ch & 1;
        if (ch + 1 < KT) {
            const int nb = (ch + 1) & 1;
            const int k0 = (ch + 1) * BK;
#pragma unroll
            for (int p = 0; p < 2; ++p) CP_ASYNC16(sA[nb] + asw[p], aptr[p] + k0);
#pragma unroll
            for (int p = 0; p < 2; ++p) CP_ASYNC16(sB[nb] + asw[p], bptr[p] + k0);
            CP_COMMIT();
            CP_WAIT(1);
        } else {
            CP_WAIT(0);
        }
        __syncthreads();

        const __half* a = As[buf];
        const __half* b = Bs[buf];
#pragma unroll
        for (int k16 = 0; k16 < BK / 16; ++k16) {
            const int kb = k16 * 16;
            uint32_t ua[4][4], ub[4][2];
#pragma unroll
            for (int mt = 0; mt < 4; ++mt) {
                const int m = m_base + mt * 16 + qid;
                const __half* ar0 = a + m * AROW + kb + 2 * tq;
                const __half* ar1 = ar0 + 8 * AROW;
                ua[mt][0] = *(const uint32_t*)(ar0);
                ua[mt][1] = *(const uint32_t*)(ar1);
                ua[mt][2] = *(const uint32_t*)(ar0 + 8);
                ua[mt][3] = *(const uint32_t*)(ar1 + 8);
            }
#pragma unroll
            for (int nt = 0; nt < 4; ++nt) {
                const int n = n_base + nt * 8 + qid;
                const __half* br = b + n * AROW + kb + 2 * tq;
                ub[nt][0] = *(const uint32_t*)(br);
                ub[nt][1] = *(const uint32_t*)(br + 8);
            }
#pragma unroll
            for (int mt = 0; mt < 4; ++mt)
#pragma unroll
                for (int nt = 0; nt < 4; ++nt)
                    mma_f16(acc[mt][nt], ua[mt][0], ua[mt][1], ua[mt][2], ua[mt][3],
                            ub[nt][0], ub[nt][1]);
        }
        __syncthreads();
    }

    // --- epilogue ---
#pragma unroll
    for (int mt = 0; mt < 4; ++mt) {
        const int r0 = row0 + m_base + mt * 16 + qid;
        const int r1 = r0 + 8;
        float ss0 = 0.0f, ss1 = 0.0f;
#pragma unroll
        for (int nt = 0; nt < 4; ++nt) {
            const int col = n0 + n_base + nt * 8 + tq * 2;
            float v0 = acc[mt][nt][0], v1 = acc[mt][nt][1];
            float v2 = acc[mt][nt][2], v3 = acc[mt][nt][3];
            if (ACT) {
                v0 = gelu_exact(v0); v1 = gelu_exact(v1);
                v2 = gelu_exact(v2); v3 = gelu_exact(v3);
                ss0 += v0 * v0 + v1 * v1;
                ss1 += v2 * v2 + v3 * v3;
                __half2 p0 = __floats2half2_rn(v0, v1);
                __half2 p1 = __floats2half2_rn(v2, v3);
                if (r0 < cnt) *(__half2*)(Ch + (size_t)(off + r0) * NC + col) = p0;
                if (r1 < cnt) *(__half2*)(Ch + (size_t)(off + r1) * NC + col) = p1;
            } else {
                if (r0 < cnt) *(float2*)(Cf + (size_t)(off + r0) * NC + col) = make_float2(v0, v1);
                if (r1 < cnt) *(float2*)(Cf + (size_t)(off + r1) * NC + col) = make_float2(v2, v3);
            }
        }
        if (ACT) {
#pragma unroll
            for (int o = 1; o < 4; o <<= 1) {
                ss0 += __shfl_xor_sync(0xFFFFFFFFu, ss0, o);
                ss1 += __shfl_xor_sync(0xFFFFFFFFu, ss1, o);
            }
            if (tq == 0) {
                if (r0 < cnt) atomicAdd(&SS[off + r0], ss0);
                if (r1 < cnt) atomicAdd(&SS[off + r1], ss1);
            }
        }
    }
}

// ---------------- rmsnorm scale kernels ----------------
// g_h1h = fp16( h1r * rsqrt(mean(h1^2)+eps) * n1 )
__global__ void scale1_kernel(const float* __restrict__ n1) {
    int idx = blockIdx.x * blockDim.x + threadIdx.x;
    int p = idx / (HDIM / 4);
    int h = (idx % (HDIM / 4)) * 4;
    if (p >= NPAIR) return;
    int e = g_pair_expert[p];
    float rs = rsqrtf(g_ss1[p] * (1.0f / HDIM) + 1e-6f);
    size_t base = (size_t)p * HDIM + h;
    uint2 raw = *(const uint2*)&g_h1r[base];
    float2 f01 = __half22float2(*(__half2*)&raw.x);
    float2 f23 = __half22float2(*(__half2*)&raw.y);
    const float* w = n1 + e * HDIM + h;
    f01.x *= rs * w[0]; f01.y *= rs * w[1];
    f23.x *= rs * w[2]; f23.y *= rs * w[3];
    __half2 o0 = __floats2half2_rn(f01.x, f01.y);
    __half2 o1 = __floats2half2_rn(f23.x, f23.y);
    *(uint2*)&g_h1h[base] = make_uint2(*(uint32_t*)&o0, *(uint32_t*)&o1);
}

// g_s2h = fp16( h2r * rsqrt(mean(h2^2)+eps) * n2 + h1h )
__global__ void scale2_kernel(const float* __restrict__ n2) {
    int idx = blockIdx.x * blockDim.x + threadIdx.x;
    int p = idx / (HDIM / 4);
    int h = (idx % (HDIM / 4)) * 4;
    if (p >= NPAIR) return;
    int e = g_pair_expert[p];
    float rs = rsqrtf(g_ss2[p] * (1.0f / HDIM) + 1e-6f);
    size_t base = (size_t)p * HDIM + h;
    uint2 raw = *(const uint2*)&g_h2r[base];
    uint2 res = *(const uint2*)&g_h1h[base];
    float2 f01 = __half22float2(*(__half2*)&raw.x);
    float2 f23 = __half22float2(*(__half2*)&raw.y);
    float2 r01 = __half22float2(*(__half2*)&res.x);
    float2 r23 = __half22float2(*(__half2*)&res.y);
    const float* w = n2 + e * HDIM + h;
    f01.x = f01.x * rs * w[0] + r01.x;
    f01.y = f01.y * rs * w[1] + r01.y;
    f23.x = f23.x * rs * w[2] + r23.x;
    f23.y = f23.y * rs * w[3] + r23.y;
    __half2 o0 = __floats2half2_rn(f01.x, f01.y);
    __half2 o1 = __floats2half2_rn(f23.x, f23.y);
    *(uint2*)&g_s2h[base] = make_uint2(*(uint32_t*)&o0, *(uint32_t*)&o1);
}

// ---------------- final gate-weighted combine ----------------
__global__ void combine_kernel(float* __restrict__ out) {
    int idx = blockIdx.x * blockDim.x + threadIdx.x;
    int t = idx / (DDIM / 4);
    int h = (idx % (DDIM / 4)) * 4;
    if (t >= NTOK) return;
    float go0 = g_gate[t * 2 + 0], go1 = g_gate[t * 2 + 1];
    int p0 = g_tok_pair[t * 2 + 0], p1 = g_tok_pair[t * 2 + 1];
    float4 y0 = *(const float4*)&g_y[(size_t)p0 * DDIM + h];
    float4 y1 = *(const float4*)&g_y[(size_t)p1 * DDIM + h];
    float4 r;
    r.x = go0 * y0.x + go1 * y1.x;
    r.y = go0 * y0.y + go1 * y1.y;
    r.z = go0 * y0.z + go1 * y1.z;
    r.w = go0 * y0.w + go1 * y1.w;
    *(float4*)&out[(size_t)t * DDIM + h] = r;
}

// ---------------- launcher ----------------
extern "C" void kernel_launch(void* const* d_in, const int* in_sizes, int n_in,
                              void* d_out, int out_size) {
    const float* x  = (const float*)d_in[0];
    const float* gw = (const float*)d_in[1];
    const float* w1 = (const float*)d_in[2];
    const float* w2 = (const float*)d_in[3];
    const float* w3 = (const float*)d_in[4];
    const float* n1 = (const float*)d_in[5];
    const float* n2 = (const float*)d_in[6];
    float* out = (float*)d_out;

    zero_kernel<<<(NPAIR + 255) / 256, 256>>>();
    gate_kernel<<<NTOK / 8, 256>>>(x, gw);
    offsets_kernel<<<1, 32>>>();
    scatter_kernel<<<NPAIR / 256, 256>>>();

    convert_x_kernel<<<(NTOK * DDIM / 4 + 255) / 256, 256>>>(x);
    transpose_w_kernel<DDIM, HDIM, 1><<<dim3(HDIM / 32, DDIM / 32, NEXP), dim3(32, 8)>>>(w1);
    transpose_w_kernel<HDIM, HDIM, 2><<<dim3(HDIM / 32, HDIM / 32, NEXP), dim3(32, 8)>>>(w2);
    transpose_w_kernel<HDIM, DDIM, 3><<<dim3(DDIM / 32, HDIM / 32, NEXP), dim3(32, 8)>>>(w3);

    moe_gemm_h<1><<<dim3(HDIM / BN, NPAIR / BM, NEXP), 256, SMEM_DYN>>>();
    scale1_kernel<<<NPAIR * (HDIM / 4) / 256, 256>>>(n1);
    moe_gemm_h<2><<<dim3(HDIM / BN, NPAIR / BM, NEXP), 256, SMEM_DYN>>>();
    scale2_kernel<<<NPAIR * (HDIM / 4) / 256, 256>>>(n2);
    moe_gemm_h<3><<<dim3(DDIM / BN, NPAIR / BM, NEXP), 256, SMEM_DYN>>>();

    combine_kernel<<<NTOK * (DDIM / 4) / 256, 256>>>(out);
}